// round 4
// baseline (speedup 1.0000x reference)
#include <cuda_runtime.h>

#define EMB 64
#define NN_MAX 160000
#define NE_MAX 4000000

// Static scratch — no runtime allocation. Buffers selected by integer tag
// inside kernels only (host code must never take a __device__ symbol address).
__device__ float g_bufA[NN_MAX * EMB];           // layer ping (40.96 MB)
__device__ float g_bufB[NN_MAX * EMB];           // layer pong (40.96 MB)
__device__ int   g_rowstart[NN_MAX + 1];
__device__ int   g_cursor[NN_MAX];               // counts -> placement cursors
__device__ int2  g_edge[NE_MAX];                 // packed {col, val_bits}, row-sorted

// ---------------------------------------------------------------------------
// 0) zero per-row counters
// ---------------------------------------------------------------------------
__global__ void zero_kernel(int nn)
{
    int i = blockIdx.x * blockDim.x + threadIdx.x;
    if (i < nn) g_cursor[i] = 0;
}

// ---------------------------------------------------------------------------
// 1) count edges per destination row (scalar loads — alignment-safe, as in R1)
// ---------------------------------------------------------------------------
__global__ void count_kernel(const int* __restrict__ erow, int ne)
{
    int e = blockIdx.x * blockDim.x + threadIdx.x;
    if (e < ne) atomicAdd(&g_cursor[erow[e]], 1);
}

// ---------------------------------------------------------------------------
// 2) single-block exclusive scan: counts -> rowstart; cursor = rowstart
// ---------------------------------------------------------------------------
__global__ void scan_kernel(int nn)
{
    __shared__ int s[1024];
    int t = threadIdx.x;
    int ch = (nn + 1023) / 1024;
    int base = t * ch;

    int sum = 0;
    for (int i = 0; i < ch; i++) {
        int idx = base + i;
        if (idx < nn) sum += g_cursor[idx];
    }
    s[t] = sum;
    __syncthreads();

    for (int off = 1; off < 1024; off <<= 1) {
        int v = (t >= off) ? s[t - off] : 0;
        __syncthreads();
        s[t] += v;
        __syncthreads();
    }

    int run = (t == 0) ? 0 : s[t - 1];
    for (int i = 0; i < ch; i++) {
        int idx = base + i;
        if (idx < nn) {
            int c = g_cursor[idx];
            g_rowstart[idx] = run;
            g_cursor[idx]   = run;
            run += c;
        }
    }
    if (t == 1023) g_rowstart[nn] = s[1023];
}

// ---------------------------------------------------------------------------
// 3) place edges: ONE 8B scattered store per edge (packed col+val).
//    Scalar input loads (alignment-safe); g_edge is naturally 8B-aligned.
// ---------------------------------------------------------------------------
__global__ void place_kernel(const int* __restrict__ erow,
                             const int* __restrict__ ecol,
                             const float* __restrict__ eval_,
                             int ne)
{
    int e = blockIdx.x * blockDim.x + threadIdx.x;
    if (e < ne) {
        int r = erow[e];
        int p = atomicAdd(&g_cursor[r], 1);
        g_edge[p] = make_int2(ecol[e], __float_as_int(eval_[e]));
    }
}

// ---------------------------------------------------------------------------
// 4) SPMM: one warp per row; lane owns dims [2*lane, 2*lane+1] as float2.
//    srcSel: 0 = g_bufA, 1 = g_bufB, 2 = gather directly from ue/ne (layer 1)
//    dstSel: 0 = g_bufA, 1 = g_bufB, 2 = none (last layer, apply *scale)
// ---------------------------------------------------------------------------
__global__ __launch_bounds__(256)
void spmm_kernel(const float2* __restrict__ ue2,
                 const float2* __restrict__ ne2,
                 float2* __restrict__ out2,
                 float scale, int srcSel, int dstSel, int nu, int nn)
{
    int gtid = blockIdx.x * blockDim.x + threadIdx.x;
    int w    = gtid >> 5;
    int lane = gtid & 31;
    if (w >= nn) return;

    int s = g_rowstart[w];
    int t = g_rowstart[w + 1];

    float ax = 0.f, ay = 0.f;
    int e = s;

    if (srcSel == 2) {
        // layer 1: gather straight from the concat(ue, ne) inputs
        for (; e + 4 <= t; e += 4) {
            int2 e0 = g_edge[e + 0], e1 = g_edge[e + 1];
            int2 e2 = g_edge[e + 2], e3 = g_edge[e + 3];
            const float2* p0 = (e0.x < nu) ? ue2 + e0.x * 32 : ne2 + (e0.x - nu) * 32;
            const float2* p1 = (e1.x < nu) ? ue2 + e1.x * 32 : ne2 + (e1.x - nu) * 32;
            const float2* p2 = (e2.x < nu) ? ue2 + e2.x * 32 : ne2 + (e2.x - nu) * 32;
            const float2* p3 = (e3.x < nu) ? ue2 + e3.x * 32 : ne2 + (e3.x - nu) * 32;
            float2 v0 = __ldg(&p0[lane]);
            float2 v1 = __ldg(&p1[lane]);
            float2 v2 = __ldg(&p2[lane]);
            float2 v3 = __ldg(&p3[lane]);
            float w0 = __int_as_float(e0.y), w1 = __int_as_float(e1.y);
            float w2 = __int_as_float(e2.y), w3 = __int_as_float(e3.y);
            ax += w0 * v0.x; ay += w0 * v0.y;
            ax += w1 * v1.x; ay += w1 * v1.y;
            ax += w2 * v2.x; ay += w2 * v2.y;
            ax += w3 * v3.x; ay += w3 * v3.y;
        }
        for (; e < t; e++) {
            int2 ed = g_edge[e];
            const float2* p = (ed.x < nu) ? ue2 + ed.x * 32 : ne2 + (ed.x - nu) * 32;
            float2 v = __ldg(&p[lane]);
            float wv = __int_as_float(ed.y);
            ax += wv * v.x; ay += wv * v.y;
        }
    } else {
        const float2* __restrict__ src =
            reinterpret_cast<const float2*>(srcSel ? g_bufB : g_bufA);
        for (; e + 4 <= t; e += 4) {
            int2 e0 = g_edge[e + 0], e1 = g_edge[e + 1];
            int2 e2 = g_edge[e + 2], e3 = g_edge[e + 3];
            float2 v0 = __ldg(&src[e0.x * 32 + lane]);
            float2 v1 = __ldg(&src[e1.x * 32 + lane]);
            float2 v2 = __ldg(&src[e2.x * 32 + lane]);
            float2 v3 = __ldg(&src[e3.x * 32 + lane]);
            float w0 = __int_as_float(e0.y), w1 = __int_as_float(e1.y);
            float w2 = __int_as_float(e2.y), w3 = __int_as_float(e3.y);
            ax += w0 * v0.x; ay += w0 * v0.y;
            ax += w1 * v1.x; ay += w1 * v1.y;
            ax += w2 * v2.x; ay += w2 * v2.y;
            ax += w3 * v3.x; ay += w3 * v3.y;
        }
        for (; e < t; e++) {
            int2 ed = g_edge[e];
            float2 v = __ldg(&src[ed.x * 32 + lane]);
            float wv = __int_as_float(ed.y);
            ax += wv * v.x; ay += wv * v.y;
        }
    }

    int idx = w * 32 + lane;
    float2 prev;
    if (srcSel == 2) {
        prev = (w < nu) ? __ldg(&ue2[w * 32 + lane])
                        : __ldg(&ne2[(w - nu) * 32 + lane]);
    } else {
        prev = out2[idx];
    }

    if (dstSel == 2) {
        out2[idx] = make_float2((prev.x + ax) * scale, (prev.y + ay) * scale);
    } else {
        float2* dst = reinterpret_cast<float2*>(dstSel ? g_bufB : g_bufA);
        dst[idx]  = make_float2(ax, ay);
        out2[idx] = make_float2(prev.x + ax, prev.y + ay);
    }
}

// ---------------------------------------------------------------------------
extern "C" void kernel_launch(void* const* d_in, const int* in_sizes, int n_in,
                              void* d_out, int out_size)
{
    const float* ue = (const float*)d_in[0];   // user_emb  [n_users, 64]
    const float* ne = (const float*)d_in[1];   // news_emb  [n_items, 64]
    const float* ev = (const float*)d_in[2];   // edge_val  [ne]
    const int*   er = (const int*)  d_in[3];   // edge_row  [ne]
    const int*   ec = (const int*)  d_in[4];   // edge_col  [ne]
    // d_in[5] = n_layers scalar; fixed at 3 for this problem.

    int n_users = in_sizes[0] / EMB;
    int n_items = in_sizes[1] / EMB;
    int nn      = n_users + n_items;
    int nedge   = in_sizes[2];

    const int T = 256;
    float2* out2 = (float2*)d_out;

    zero_kernel<<<(nn + T - 1) / T, T>>>(nn);
    count_kernel<<<(nedge + T - 1) / T, T>>>(er, nedge);
    scan_kernel<<<1, 1024>>>(nn);
    place_kernel<<<(nedge + T - 1) / T, T>>>(er, ec, ev, nedge);

    int blocks = (nn * 32 + T - 1) / T;
    const float inv = 0.25f;   // 1/(n_layers+1)

    // layer 1: src = inputs (tag 2), dst = bufB; out = emb + l1
    spmm_kernel<<<blocks, T>>>((const float2*)ue, (const float2*)ne, out2,
                               inv, /*srcSel=*/2, /*dstSel=*/1, n_users, nn);
    // layer 2: src = bufB, dst = bufA; out += l2
    spmm_kernel<<<blocks, T>>>((const float2*)ue, (const float2*)ne, out2,
                               inv, /*srcSel=*/1, /*dstSel=*/0, n_users, nn);
    // layer 3 (last): src = bufA; out = (out + l3) * 0.25
    spmm_kernel<<<blocks, T>>>((const float2*)ue, (const float2*)ne, out2,
                               inv, /*srcSel=*/0, /*dstSel=*/2, n_users, nn);
}

// round 7
// speedup vs baseline: 1.0507x; 1.0507x over previous
#include <cuda_runtime.h>

#define EMB 64
#define NN_MAX 160000
#define NE_MAX 4000000

// Static scratch — no runtime allocation. Buffers selected by integer tag
// inside kernels only (host code must never take a __device__ symbol address).
__device__ float g_bufA[NN_MAX * EMB];           // layer ping (40.96 MB)
__device__ float g_bufB[NN_MAX * EMB];           // layer pong (40.96 MB)
__device__ int   g_rowstart[NN_MAX + 1];
__device__ int   g_cursor[NN_MAX];               // counts -> placement cursors
__device__ int2  g_edge[NE_MAX];                 // packed {col, val_bits}, row-sorted

// ---------------------------------------------------------------------------
// 1) init: bufA = concat(user_emb, news_emb) (L2 warm-up for layer-1 gathers);
//    also zeroes the per-row counters. float2 input loads only — that access
//    width on ue/ne is the proven-safe one (used by every passing SPMM).
// ---------------------------------------------------------------------------
__global__ void init_kernel(const float2* __restrict__ ue,
                            const float2* __restrict__ ne,
                            int n_user2, int n_total2, int nn)
{
    int i = blockIdx.x * blockDim.x + threadIdx.x;
    if (i < n_total2) {
        float2 v = (i < n_user2) ? __ldg(&ue[i]) : __ldg(&ne[i - n_user2]);
        reinterpret_cast<float2*>(g_bufA)[i] = v;
    }
    if (i < nn) g_cursor[i] = 0;
}

// ---------------------------------------------------------------------------
// 2) count edges per destination row (scalar loads — alignment-safe)
// ---------------------------------------------------------------------------
__global__ void count_kernel(const int* __restrict__ erow, int ne)
{
    int e = blockIdx.x * blockDim.x + threadIdx.x;
    if (e < ne) atomicAdd(&g_cursor[erow[e]], 1);
}

// ---------------------------------------------------------------------------
// 3) single-block exclusive scan: counts -> rowstart; cursor = rowstart
// ---------------------------------------------------------------------------
__global__ void scan_kernel(int nn)
{
    __shared__ int s[1024];
    int t = threadIdx.x;
    int ch = (nn + 1023) / 1024;
    int base = t * ch;

    int sum = 0;
    for (int i = 0; i < ch; i++) {
        int idx = base + i;
        if (idx < nn) sum += g_cursor[idx];
    }
    s[t] = sum;
    __syncthreads();

    for (int off = 1; off < 1024; off <<= 1) {
        int v = (t >= off) ? s[t - off] : 0;
        __syncthreads();
        s[t] += v;
        __syncthreads();
    }

    int run = (t == 0) ? 0 : s[t - 1];
    for (int i = 0; i < ch; i++) {
        int idx = base + i;
        if (idx < nn) {
            int c = g_cursor[idx];
            g_rowstart[idx] = run;
            g_cursor[idx]   = run;
            run += c;
        }
    }
    if (t == 1023) g_rowstart[nn] = s[1023];
}

// ---------------------------------------------------------------------------
// 4) place edges: ONE 8B scattered store per edge (packed col+val).
// ---------------------------------------------------------------------------
__global__ void place_kernel(const int* __restrict__ erow,
                             const int* __restrict__ ecol,
                             const float* __restrict__ eval_,
                             int ne)
{
    int e = blockIdx.x * blockDim.x + threadIdx.x;
    if (e < ne) {
        int r = erow[e];
        int p = atomicAdd(&g_cursor[r], 1);
        g_edge[p] = make_int2(ecol[e], __float_as_int(eval_[e]));
    }
}

// ---------------------------------------------------------------------------
// 5) SPMM: one warp per row; lane owns dims [2*lane, 2*lane+1] as float2.
//    srcSel: 0 = g_bufA, 1 = g_bufB (gather source)
//    Non-last layers: dst = sum only (no accumulator RMW).
//    Last layer:      out = (emb + l1(bufB) + l2(bufA) + sum) * scale.
// ---------------------------------------------------------------------------
__global__ __launch_bounds__(256)
void spmm_kernel(const float2* __restrict__ ue2,
                 const float2* __restrict__ ne2,
                 float2* __restrict__ out2,
                 float scale, int srcSel, int dstSel, int last,
                 int nu, int nn)
{
    int gtid = blockIdx.x * blockDim.x + threadIdx.x;
    int w    = gtid >> 5;
    int lane = gtid & 31;
    if (w >= nn) return;

    const float2* __restrict__ src =
        reinterpret_cast<const float2*>(srcSel ? g_bufB : g_bufA);

    int s = g_rowstart[w];
    int t = g_rowstart[w + 1];

    float ax = 0.f, ay = 0.f;
    int e = s;

    // 8-deep unroll: 8 independent gathers in flight per warp
    for (; e + 8 <= t; e += 8) {
        int2 e0 = g_edge[e + 0], e1 = g_edge[e + 1];
        int2 e2 = g_edge[e + 2], e3 = g_edge[e + 3];
        int2 e4 = g_edge[e + 4], e5 = g_edge[e + 5];
        int2 e6 = g_edge[e + 6], e7 = g_edge[e + 7];
        float2 v0 = __ldg(&src[e0.x * 32 + lane]);
        float2 v1 = __ldg(&src[e1.x * 32 + lane]);
        float2 v2 = __ldg(&src[e2.x * 32 + lane]);
        float2 v3 = __ldg(&src[e3.x * 32 + lane]);
        float2 v4 = __ldg(&src[e4.x * 32 + lane]);
        float2 v5 = __ldg(&src[e5.x * 32 + lane]);
        float2 v6 = __ldg(&src[e6.x * 32 + lane]);
        float2 v7 = __ldg(&src[e7.x * 32 + lane]);
        float w0 = __int_as_float(e0.y), w1 = __int_as_float(e1.y);
        float w2 = __int_as_float(e2.y), w3 = __int_as_float(e3.y);
        float w4 = __int_as_float(e4.y), w5 = __int_as_float(e5.y);
        float w6 = __int_as_float(e6.y), w7 = __int_as_float(e7.y);
        ax += w0 * v0.x; ay += w0 * v0.y;
        ax += w1 * v1.x; ay += w1 * v1.y;
        ax += w2 * v2.x; ay += w2 * v2.y;
        ax += w3 * v3.x; ay += w3 * v3.y;
        ax += w4 * v4.x; ay += w4 * v4.y;
        ax += w5 * v5.x; ay += w5 * v5.y;
        ax += w6 * v6.x; ay += w6 * v6.y;
        ax += w7 * v7.x; ay += w7 * v7.y;
    }
    for (; e + 4 <= t; e += 4) {
        int2 e0 = g_edge[e + 0], e1 = g_edge[e + 1];
        int2 e2 = g_edge[e + 2], e3 = g_edge[e + 3];
        float2 v0 = __ldg(&src[e0.x * 32 + lane]);
        float2 v1 = __ldg(&src[e1.x * 32 + lane]);
        float2 v2 = __ldg(&src[e2.x * 32 + lane]);
        float2 v3 = __ldg(&src[e3.x * 32 + lane]);
        float w0 = __int_as_float(e0.y), w1 = __int_as_float(e1.y);
        float w2 = __int_as_float(e2.y), w3 = __int_as_float(e3.y);
        ax += w0 * v0.x; ay += w0 * v0.y;
        ax += w1 * v1.x; ay += w1 * v1.y;
        ax += w2 * v2.x; ay += w2 * v2.y;
        ax += w3 * v3.x; ay += w3 * v3.y;
    }
    for (; e < t; e++) {
        int2 ed = g_edge[e];
        float2 v = __ldg(&src[ed.x * 32 + lane]);
        float wv = __int_as_float(ed.y);
        ax += wv * v.x; ay += wv * v.y;
    }

    int idx = w * 32 + lane;
    if (last) {
        // l1 = bufB row, l2 = bufA row (== src here), emb from inputs
        const float2* __restrict__ l1p = reinterpret_cast<const float2*>(g_bufB);
        const float2* __restrict__ l2p = reinterpret_cast<const float2*>(g_bufA);
        float2 l1  = l1p[idx];
        float2 l2  = l2p[idx];
        float2 emb = (w < nu) ? __ldg(&ue2[idx])
                              : __ldg(&ne2[(w - nu) * 32 + lane]);
        out2[idx] = make_float2((emb.x + l1.x + l2.x + ax) * scale,
                                (emb.y + l1.y + l2.y + ay) * scale);
    } else {
        float2* dst = reinterpret_cast<float2*>(dstSel ? g_bufB : g_bufA);
        dst[idx] = make_float2(ax, ay);
    }
}

// ---------------------------------------------------------------------------
extern "C" void kernel_launch(void* const* d_in, const int* in_sizes, int n_in,
                              void* d_out, int out_size)
{
    const float* ue = (const float*)d_in[0];   // user_emb  [n_users, 64]
    const float* ne = (const float*)d_in[1];   // news_emb  [n_items, 64]
    const float* ev = (const float*)d_in[2];   // edge_val  [ne]
    const int*   er = (const int*)  d_in[3];   // edge_row  [ne]
    const int*   ec = (const int*)  d_in[4];   // edge_col  [ne]
    // d_in[5] = n_layers scalar; fixed at 3 for this problem.

    int n_users = in_sizes[0] / EMB;
    int n_items = in_sizes[1] / EMB;
    int nn      = n_users + n_items;
    int nedge   = in_sizes[2];

    int n_user2  = n_users * (EMB / 2);
    int n_total2 = nn * (EMB / 2);

    const int T = 256;
    float2* out2 = (float2*)d_out;

    init_kernel<<<(n_total2 + T - 1) / T, T>>>(
        (const float2*)ue, (const float2*)ne, n_user2, n_total2, nn);
    count_kernel<<<(nedge + T - 1) / T, T>>>(er, nedge);
    scan_kernel<<<1, 1024>>>(nn);
    place_kernel<<<(nedge + T - 1) / T, T>>>(er, ec, ev, nedge);

    int blocks = (nn * 32 + T - 1) / T;
    const float inv = 0.25f;   // 1/(n_layers+1)

    // layer 1: src = bufA (emb copy) -> l1 in bufB
    spmm_kernel<<<blocks, T>>>((const float2*)ue, (const float2*)ne, out2,
                               inv, /*srcSel=*/0, /*dstSel=*/1, /*last=*/0,
                               n_users, nn);
    // layer 2: src = bufB -> l2 in bufA (emb copy no longer needed)
    spmm_kernel<<<blocks, T>>>((const float2*)ue, (const float2*)ne, out2,
                               inv, /*srcSel=*/1, /*dstSel=*/0, /*last=*/0,
                               n_users, nn);
    // layer 3 (last): src = bufA; out = (emb + bufB + bufA + sum) * 0.25
    spmm_kernel<<<blocks, T>>>((const float2*)ue, (const float2*)ne, out2,
                               inv, /*srcSel=*/0, /*dstSel=*/0, /*last=*/1,
                               n_users, nn);
}